// round 14
// baseline (speedup 1.0000x reference)
#include <cuda_runtime.h>
#include <cuda_bf16.h>
#include <cstdint>

#define B_ 8
#define P_ 64
#define S_ 256
#define D_ 256

// ---------------- device scratch (zero-init at load; reset each run) ----------------
__device__ float g_partials[P_ * 32 * 5];
__device__ float g_redhalf[2048 * 64];     // per-(p,b,q) pair: follower's partial red
__device__ int   g_pflag[2048];
__device__ float g_scale[P_];
__device__ float g_bias[P_];
__device__ int   g_cnt[P_];
__device__ int   g_cnt2[P_];
__device__ int   g_flag[P_];

__device__ __forceinline__ uint32_t smem_to_u32(const void* p) {
    uint32_t a;
    asm("{ .reg .u64 t; cvta.to.shared.u64 t, %1; cvt.u32.u64 %0, t; }" : "=r"(a) : "l"(p));
    return a;
}
__device__ __forceinline__ uint32_t bits2(__nv_bfloat162 v) {
    return *reinterpret_cast<uint32_t*>(&v);
}

#define LDSM4(d0, d1, d2, d3, a) \
    asm volatile("ldmatrix.sync.aligned.m8n8.x4.shared.b16 {%0,%1,%2,%3}, [%4];" \
                 : "=r"(d0), "=r"(d1), "=r"(d2), "=r"(d3) : "r"(a))

#define HMMA(c, a0, a1, a2, a3, b0, b1) \
    asm volatile("mma.sync.aligned.m16n8k16.row.col.f32.bf16.bf16.f32 " \
                 "{%0,%1,%2,%3}, {%4,%5,%6,%7}, {%8,%9}, {%0,%1,%2,%3};" \
                 : "+f"((c)[0]), "+f"((c)[1]), "+f"((c)[2]), "+f"((c)[3]) \
                 : "r"(a0), "r"(a1), "r"(a2), "r"(a3), "r"(b0), "r"(b1))

#define PF_L2(a) asm volatile("prefetch.global.L2 [%0];" :: "l"(a))

// ---------------- smem layout (bytes) ----------------
constexpr int ROWB   = 272;                 // 128 k *2B + 16B pad (ldmatrix conflict-free)
constexpr int OFF_A  = 128 * ROWB;          // A region (when disjoint): 34816
constexpr int OFF_RSF = OFF_A + 64 * ROWB;  // persistent rowsum: 52224, 64*4
constexpr int OFF_S2F = OFF_RSF + 256;      // 52480
constexpr int SMEM_BYTES = OFF_S2F + 256;   // 52736 -> 4 CTAs/SM
// epilogue overlay (buffer region dead after last MMA; RSF/S2F persist above it):
constexpr int OFF_REDP = 0;                 // 64*17*4 = 4352
constexpr int OFF_RED  = 4352;              // 256
constexpr int OFF_W8   = 4608;              // 160
constexpr int OFF_BC   = 4768;              // 8

// =====================================================================
// CTA = (b, p, q, nh): rows [q*64,+64) x t-cols [nh*128,+128).
// 256 thr, 4 CTA/SM (64 regs). K=128 chunks (2). Rowsums fused into convert.
// =====================================================================
__global__ void __launch_bounds__(256, 4)
da_fused_kernel(const float* __restrict__ x, const float* __restrict__ w,
                const float* __restrict__ gamma, const float* __restrict__ beta,
                float* __restrict__ out)
{
    extern __shared__ __align__(16) char sm[];
    const uint32_t smb = smem_to_u32(sm);
    const int tid = threadIdx.x, wid = tid >> 5, lane = tid & 31;
    const int bx = blockIdx.x;                 // 0..63 = b*8 + q*2 + nh
    const int nh = bx & 1, q = (bx >> 1) & 3, b = bx >> 3;
    const int p = blockIdx.y;
    const int m0 = q * 64;                     // global row base
    const int nb0 = nh * 128;                  // global t-col base
    const int pair = ((p * 8 + b) * 4 + q);
    const float* xbp = x + (size_t)(b * P_ + p) * (S_ * D_);
    const float* wp  = w + ((size_t)p << 16);

    // prefetch this CTA's W half-tile (32KB) into L2
    {
        const float* wt = wp + (size_t)(m0 + (tid >> 2)) * 256 + nb0 + (tid & 3) * 32;
        PF_L2(wt);
    }

    const int warp_m = wid >> 2;   // 0..1 : 32 m-rows
    const int warp_n = wid & 3;    // 0..3 : 32 n-cols

    float acc[2][4][4];
    #pragma unroll
    for (int mi = 0; mi < 2; ++mi)
        #pragma unroll
        for (int nf = 0; nf < 4; ++nf)
            #pragma unroll
            for (int qq = 0; qq < 4; ++qq) acc[mi][nf][qq] = 0.f;

    const bool contained = ((q >> 1) == nh);
    const uint32_t aBase = contained ? smb + (uint32_t)(m0 - nb0) * ROWB
                                     : smb + OFF_A;

    const uint32_t lrow = lane & 15;
    const uint32_t lcol = (lane >> 4) * 16;
    uint32_t aaddr[2], baddr[2];
    #pragma unroll
    for (int mi = 0; mi < 2; ++mi)
        aaddr[mi] = aBase + (uint32_t)(warp_m * 32 + mi * 16 + lrow) * ROWB + lcol;
    #pragma unroll
    for (int nj = 0; nj < 2; ++nj)
        baddr[nj] = smb + (uint32_t)(warp_n * 32 + nj * 16 + lrow) * ROWB + lcol;

    // convert mapping: 16 threads per row (8 floats each), 16 rows per pass
    const int r0 = tid >> 4;       // 0..15
    const int g8 = tid & 15;       // 8-float group within 128-k chunk

    float* rs_f = reinterpret_cast<float*>(sm + OFF_RSF);
    float* s2_f = reinterpret_cast<float*>(sm + OFF_S2F);
    if (tid < 64) { rs_f[tid] = 0.f; s2_f[tid] = 0.f; }

    // ================= k-chunk loop (2 chunks of K=128) =================
    for (int kc = 0; kc < 2; ++kc) {
        __syncthreads();
        // ---- B slice: 128 rows, batches of 2 rows (4 float4 live) ----
        #pragma unroll
        for (int h = 0; h < 4; ++h) {
            float4 pv[4];
            #pragma unroll
            for (int j = 0; j < 2; ++j) {
                int row = r0 + 16 * (h * 2 + j);
                const float* src = xbp + (size_t)(nb0 + row) * D_ + kc * 128 + g8 * 8;
                pv[j * 2]     = __ldg(reinterpret_cast<const float4*>(src));
                pv[j * 2 + 1] = __ldg(reinterpret_cast<const float4*>(src + 4));
            }
            #pragma unroll
            for (int j = 0; j < 2; ++j) {
                int row = r0 + 16 * (h * 2 + j);
                float4 a = pv[j * 2], c = pv[j * 2 + 1];
                uint4 st = make_uint4(bits2(__floats2bfloat162_rn(a.x, a.y)),
                                      bits2(__floats2bfloat162_rn(a.z, a.w)),
                                      bits2(__floats2bfloat162_rn(c.x, c.y)),
                                      bits2(__floats2bfloat162_rn(c.z, c.w)));
                *reinterpret_cast<uint4*>(sm + (size_t)row * ROWB + g8 * 16) = st;
                // fused rowsum for leader's own rows (warp-uniform branch)
                if (nh == 0) {
                    int rl = row - m0;         // nb0 == 0 for leader
                    if (rl >= 0 && rl < 64) {
                        float s  = a.x + a.y + a.z + a.w + c.x + c.y + c.z + c.w;
                        float s2 = a.x * a.x + a.y * a.y + a.z * a.z + a.w * a.w
                                 + c.x * c.x + c.y * c.y + c.z * c.z + c.w * c.w;
                        #pragma unroll
                        for (int o = 8; o; o >>= 1) {
                            s  += __shfl_xor_sync(0xffffffffu, s, o);
                            s2 += __shfl_xor_sync(0xffffffffu, s2, o);
                        }
                        if (g8 == 0) { rs_f[rl] += s; s2_f[rl] += s2; }
                    }
                }
            }
        }
        // ---- A slice (64 rows) when disjoint ----
        if (!contained) {
            #pragma unroll
            for (int h = 0; h < 2; ++h) {
                float4 pv[4];
                #pragma unroll
                for (int j = 0; j < 2; ++j) {
                    int row = r0 + 16 * (h * 2 + j);
                    const float* src = xbp + (size_t)(m0 + row) * D_ + kc * 128 + g8 * 8;
                    pv[j * 2]     = __ldg(reinterpret_cast<const float4*>(src));
                    pv[j * 2 + 1] = __ldg(reinterpret_cast<const float4*>(src + 4));
                }
                #pragma unroll
                for (int j = 0; j < 2; ++j) {
                    int row = r0 + 16 * (h * 2 + j);
                    float4 a = pv[j * 2], c = pv[j * 2 + 1];
                    uint4 st = make_uint4(bits2(__floats2bfloat162_rn(a.x, a.y)),
                                          bits2(__floats2bfloat162_rn(a.z, a.w)),
                                          bits2(__floats2bfloat162_rn(c.x, c.y)),
                                          bits2(__floats2bfloat162_rn(c.z, c.w)));
                    *reinterpret_cast<uint4*>(sm + OFF_A + (size_t)row * ROWB + g8 * 16) = st;
                    if (nh == 0) {   // leader's own rows
                        float s  = a.x + a.y + a.z + a.w + c.x + c.y + c.z + c.w;
                        float s2 = a.x * a.x + a.y * a.y + a.z * a.z + a.w * a.w
                                 + c.x * c.x + c.y * c.y + c.z * c.z + c.w * c.w;
                        #pragma unroll
                        for (int o = 8; o; o >>= 1) {
                            s  += __shfl_xor_sync(0xffffffffu, s, o);
                            s2 += __shfl_xor_sync(0xffffffffu, s2, o);
                        }
                        if (g8 == 0) { rs_f[row] += s; s2_f[row] += s2; }
                    }
                }
            }
        }
        __syncthreads();

        // ---- MMA: 8 K16-steps over the 128-k chunk ----
        #pragma unroll
        for (int ks = 0; ks < 8; ++ks) {
            const uint32_t ko = (uint32_t)ks * 32;
            uint32_t ah[2][4], bh[2][4];
            #pragma unroll
            for (int mi = 0; mi < 2; ++mi)
                LDSM4(ah[mi][0], ah[mi][1], ah[mi][2], ah[mi][3], aaddr[mi] + ko);
            #pragma unroll
            for (int nj = 0; nj < 2; ++nj)
                LDSM4(bh[nj][0], bh[nj][1], bh[nj][2], bh[nj][3], baddr[nj] + ko);
            #pragma unroll
            for (int nj = 0; nj < 2; ++nj)
                #pragma unroll
                for (int nk = 0; nk < 2; ++nk) {
                    const int nf = nj * 2 + nk;
                    #pragma unroll
                    for (int mi = 0; mi < 2; ++mi)
                        HMMA(acc[mi][nf], ah[mi][0], ah[mi][1], ah[mi][2], ah[mi][3],
                             bh[nj][nk], bh[nj][2 + nk]);
                }
        }
    }
    __syncthreads();   // buffer dead -> overlay usable (RSF/S2F persist above)

    // ================= fold W (own n-half) into per-row partials =================
    float* redp = reinterpret_cast<float*>(sm + OFF_REDP);
    #pragma unroll
    for (int mi = 0; mi < 2; ++mi)
        #pragma unroll
        for (int half = 0; half < 2; ++half) {
            int rl = warp_m * 32 + mi * 16 + (lane >> 2) + half * 8;   // 0..63 local
            const float* wr = wp + (size_t)(m0 + rl) * 256 + nb0 + warp_n * 32 + (lane & 3) * 2;
            float part = 0.f;
            #pragma unroll
            for (int nf = 0; nf < 4; ++nf) {
                float2 wv = __ldg(reinterpret_cast<const float2*>(
                    wr + (nf >> 1) * 16 + (nf & 1) * 8));
                part = fmaf(acc[mi][nf][half * 2 + 0], wv.x, part);
                part = fmaf(acc[mi][nf][half * 2 + 1], wv.y, part);
            }
            redp[rl * 17 + warp_n * 4 + (lane & 3)] = part;
        }
    __syncthreads();

    // reduce 16 partials per row -> this CTA's (unscaled) half-red
    float rsum = 0.f;
    if (tid < 64) {
        #pragma unroll
        for (int l = 0; l < 16; ++l) rsum += redp[tid * 17 + l];
    }

    // ================= follower: publish half-red and exit =================
    if (nh == 1) {
        if (tid < 64) {
            g_redhalf[pair * 64 + tid] = rsum;
            __threadfence();
        }
        __syncthreads();
        if (tid == 0) atomicExch(&g_pflag[pair], 1);
        return;
    }

    // ================= leader: wait for sibling's half-red =================
    if (tid == 0) {
        volatile int* fl = (volatile int*)&g_pflag[pair];
        while (*fl == 0) __nanosleep(32);
        __threadfence();
    }
    __syncthreads();

    // ================= merge red + BN vals (rowsums already in smem) =================
    float* redsm = reinterpret_cast<float*>(sm + OFF_RED);
    float vals[5] = {0.f, 0.f, 0.f, 0.f, 0.f};
    if (tid < 64) {
        float sib = g_redhalf[pair * 64 + tid];
        float red = (rsum + sib) * 0.0625f;     // 1/sqrt(256)
        redsm[tid] = red;
        float xr = rs_f[tid], x2 = s2_f[tid];
        vals[0] = xr; vals[1] = x2; vals[2] = red; vals[3] = red * red; vals[4] = red * xr;
    }
    float* w8 = reinterpret_cast<float*>(sm + OFF_W8);
    #pragma unroll
    for (int qq = 0; qq < 5; ++qq) {
        float v = vals[qq];
        #pragma unroll
        for (int o = 16; o; o >>= 1) v += __shfl_xor_sync(0xffffffffu, v, o);
        if (lane == 0) w8[wid * 5 + qq] = v;
    }
    __syncthreads();
    if (tid == 32) g_pflag[pair] = 0;          // reset for next graph replay

    // ================= cross-CTA BN handshake (32 leaders per channel) =================
    float* bc = reinterpret_cast<float*>(sm + OFF_BC);
    if (tid == 0) {
        int slot = (p * 32 + b * 4 + q) * 5;
        #pragma unroll
        for (int qq = 0; qq < 5; ++qq) {
            float r = 0.f;
            for (int t = 0; t < 8; ++t) r += w8[t * 5 + qq];
            g_partials[slot + qq] = r;
        }
        __threadfence();
        int o = atomicAdd(&g_cnt[p], 1);
        if (o == 31) {
            __threadfence();
            float sx = 0.f, sx2 = 0.f, sr = 0.f, sr2 = 0.f, cr = 0.f;
            for (int c = 0; c < 32; ++c) {
                const float* qp = g_partials + (p * 32 + c) * 5;
                sx += qp[0]; sx2 += qp[1]; sr += qp[2]; sr2 += qp[3]; cr += qp[4];
            }
            const float N = (float)(B_ * S_ * D_);
            float sumy  = sx + (float)D_ * sr;
            float sumy2 = sx2 + 2.f * cr + (float)D_ * sr2;
            float mean = sumy / N;
            float var  = sumy2 / N - mean * mean;
            float sc = __ldg(gamma + p) * rsqrtf(var + 1e-5f);
            g_scale[p] = sc;
            g_bias[p]  = __ldg(beta + p) - mean * sc;
            __threadfence();
            atomicExch(&g_flag[p], 1);
        }
        volatile int* fl = (volatile int*)&g_flag[p];
        while (*fl == 0) __nanosleep(64);
        __threadfence();
        bc[0] = g_scale[p];
        bc[1] = g_bias[p];
        int o2 = atomicAdd(&g_cnt2[p], 1);
        if (o2 == 31) {        // all consumers done: reset for next graph replay
            g_flag[p] = 0; g_cnt[p] = 0; g_cnt2[p] = 0;
        }
    }
    __syncthreads();
    const float sc = bc[0], bi = bc[1];

    // ================= output: out = (x + red) * sc + bi (x from L2) =================
    float* ob = out + ((size_t)(b * P_ + p) << 16) + (size_t)m0 * 256;
    #pragma unroll
    for (int j = 0; j < 8; ++j) {
        int r = wid * 8 + j;
        float red = redsm[r];
        const float* xr = xbp + (size_t)(m0 + r) * 256;
        #pragma unroll
        for (int it = 0; it < 2; ++it) {
            float4 v = __ldg(reinterpret_cast<const float4*>(xr + it * 128 + lane * 4));
            v.x = fmaf(v.x + red, sc, bi);
            v.y = fmaf(v.y + red, sc, bi);
            v.z = fmaf(v.z + red, sc, bi);
            v.w = fmaf(v.w + red, sc, bi);
            *reinterpret_cast<float4*>(ob + (size_t)r * 256 + it * 128 + lane * 4) = v;
        }
    }
}

// =====================================================================
extern "C" void kernel_launch(void* const* d_in, const int* in_sizes, int n_in,
                              void* d_out, int out_size)
{
    const float* x     = (const float*)d_in[0];
    const float* w     = (const float*)d_in[1];
    const float* gamma = (const float*)d_in[2];
    const float* beta  = (const float*)d_in[3];
    float* out = (float*)d_out;

    cudaFuncSetAttribute(da_fused_kernel,
                         cudaFuncAttributeMaxDynamicSharedMemorySize, SMEM_BYTES);

    dim3 grid(64, P_);   // blockIdx.x = b*8+q*2+nh (pairs adjacent, channels contiguous)
    da_fused_kernel<<<grid, 256, SMEM_BYTES>>>(x, w, gamma, beta, out);
}

// round 15
// speedup vs baseline: 1.1019x; 1.1019x over previous
#include <cuda_runtime.h>
#include <cuda_bf16.h>
#include <cstdint>

#define B_ 8
#define P_ 64
#define S_ 256
#define D_ 256

// ---------------- device scratch (zero-init at load; reset each run) ----------------
__device__ float g_partials[P_ * 32 * 5];
__device__ float g_redhalf[2048 * 64];     // per-(p,b,q) pair: follower's partial red
__device__ int   g_pflag[2048];
__device__ float g_scale[P_];
__device__ float g_bias[P_];
__device__ int   g_cnt[P_];
__device__ int   g_cnt2[P_];
__device__ int   g_flag[P_];

__device__ __forceinline__ uint32_t smem_to_u32(const void* p) {
    uint32_t a;
    asm("{ .reg .u64 t; cvta.to.shared.u64 t, %1; cvt.u32.u64 %0, t; }" : "=r"(a) : "l"(p));
    return a;
}
__device__ __forceinline__ uint32_t bits2(__nv_bfloat162 v) {
    return *reinterpret_cast<uint32_t*>(&v);
}

#define LDSM4(d0, d1, d2, d3, a) \
    asm volatile("ldmatrix.sync.aligned.m8n8.x4.shared.b16 {%0,%1,%2,%3}, [%4];" \
                 : "=r"(d0), "=r"(d1), "=r"(d2), "=r"(d3) : "r"(a))

#define HMMA(c, a0, a1, a2, a3, b0, b1) \
    asm volatile("mma.sync.aligned.m16n8k16.row.col.f32.bf16.bf16.f32 " \
                 "{%0,%1,%2,%3}, {%4,%5,%6,%7}, {%8,%9}, {%0,%1,%2,%3};" \
                 : "+f"((c)[0]), "+f"((c)[1]), "+f"((c)[2]), "+f"((c)[3]) \
                 : "r"(a0), "r"(a1), "r"(a2), "r"(a3), "r"(b0), "r"(b1))

#define PF_L2(a) asm volatile("prefetch.global.L2 [%0];" :: "l"(a))

// ---------------- smem layout (bytes) ----------------
constexpr int ROWB   = 144;                 // 64 k *2B + 16B pad (ldmatrix conflict-free)
constexpr int OFF_A  = 128 * ROWB;          // A region (when disjoint): 18432
constexpr int SMEM_BYTES = OFF_A + 64 * ROWB;   // 27648 -> 4 CTAs/SM
// epilogue overlay (buffer dead after last MMA):
constexpr int OFF_REDP = 0;                 // 64*17*4 = 4352
constexpr int OFF_RS   = 4352;              // 256
constexpr int OFF_S2   = 4608;              // 256
constexpr int OFF_RED  = 4864;              // 256
constexpr int OFF_W8   = 5120;              // 160
constexpr int OFF_BC   = 5280;              // 8

// =====================================================================
// CTA = (b, p, q, nh): rows [q*64,+64) x t-cols [nh*128,+128).
// 256 thr, 4 CTA/SM (64 regs). Convert uses 16B STS (8 thr/row).
// =====================================================================
__global__ void __launch_bounds__(256, 4)
da_fused_kernel(const float* __restrict__ x, const float* __restrict__ w,
                const float* __restrict__ gamma, const float* __restrict__ beta,
                float* __restrict__ out)
{
    extern __shared__ __align__(16) char sm[];
    const uint32_t smb = smem_to_u32(sm);
    const int tid = threadIdx.x, wid = tid >> 5, lane = tid & 31;
    const int bx = blockIdx.x;                 // 0..63 = b*8 + q*2 + nh
    const int nh = bx & 1, q = (bx >> 1) & 3, b = bx >> 3;
    const int p = blockIdx.y;
    const int m0 = q * 64;                     // global row base
    const int nb0 = nh * 128;                  // global t-col base
    const int pair = ((p * 8 + b) * 4 + q);
    const float* xbp = x + (size_t)(b * P_ + p) * (S_ * D_);
    const float* wp  = w + ((size_t)p << 16);

    // prefetch this CTA's W half-tile (32KB) into L2
    {
        const float* wt = wp + (size_t)(m0 + (tid >> 2)) * 256 + nb0 + (tid & 3) * 32;
        PF_L2(wt);
    }

    const int warp_m = wid >> 2;   // 0..1 : 32 m-rows
    const int warp_n = wid & 3;    // 0..3 : 32 n-cols

    // accumulators: 2 m-frags x 4 n-frags x 4 = 32 regs
    float acc[2][4][4];
    #pragma unroll
    for (int mi = 0; mi < 2; ++mi)
        #pragma unroll
        for (int nf = 0; nf < 4; ++nf)
            #pragma unroll
            for (int qq = 0; qq < 4; ++qq) acc[mi][nf][qq] = 0.f;

    const bool contained = ((q >> 1) == nh);   // A rows inside B slice?
    const uint32_t aBase = contained ? smb + (uint32_t)(m0 - nb0) * ROWB
                                     : smb + OFF_A;

    const uint32_t lrow = lane & 15;
    const uint32_t lcol = (lane >> 4) * 16;
    uint32_t aaddr[2], baddr[2];
    #pragma unroll
    for (int mi = 0; mi < 2; ++mi)
        aaddr[mi] = aBase + (uint32_t)(warp_m * 32 + mi * 16 + lrow) * ROWB + lcol;
    #pragma unroll
    for (int nj = 0; nj < 2; ++nj)
        baddr[nj] = smb + (uint32_t)(warp_n * 32 + nj * 16 + lrow) * ROWB + lcol;

    // convert mapping: 8 threads per row (8 floats -> one 16B STS), 32 rows/pass
    const int r0 = tid >> 3;       // 0..31
    const int g8 = tid & 7;        // 8-float group within 64-k chunk

    // ================= k-chunk loop (4 chunks of K=64) =================
    for (int kc = 0; kc < 4; ++kc) {
        __syncthreads();
        // ---- B slice: 128 rows = 4 row-passes, batched 2 rows (4 float4 live) ----
        #pragma unroll
        for (int h = 0; h < 2; ++h) {
            float4 pv[4];
            #pragma unroll
            for (int j = 0; j < 2; ++j) {
                int row = r0 + 32 * (h * 2 + j);
                const float* src = xbp + (size_t)(nb0 + row) * D_ + kc * 64 + g8 * 8;
                pv[j * 2]     = __ldg(reinterpret_cast<const float4*>(src));
                pv[j * 2 + 1] = __ldg(reinterpret_cast<const float4*>(src + 4));
            }
            #pragma unroll
            for (int j = 0; j < 2; ++j) {
                int row = r0 + 32 * (h * 2 + j);
                float4 a = pv[j * 2], c = pv[j * 2 + 1];
                uint4 st = make_uint4(bits2(__floats2bfloat162_rn(a.x, a.y)),
                                      bits2(__floats2bfloat162_rn(a.z, a.w)),
                                      bits2(__floats2bfloat162_rn(c.x, c.y)),
                                      bits2(__floats2bfloat162_rn(c.z, c.w)));
                *reinterpret_cast<uint4*>(sm + (size_t)row * ROWB + g8 * 16) = st;
            }
        }
        // ---- A slice (64 rows = 2 row-passes, one batch) when disjoint ----
        if (!contained) {
            float4 pv[4];
            #pragma unroll
            for (int j = 0; j < 2; ++j) {
                int row = r0 + 32 * j;
                const float* src = xbp + (size_t)(m0 + row) * D_ + kc * 64 + g8 * 8;
                pv[j * 2]     = __ldg(reinterpret_cast<const float4*>(src));
                pv[j * 2 + 1] = __ldg(reinterpret_cast<const float4*>(src + 4));
            }
            #pragma unroll
            for (int j = 0; j < 2; ++j) {
                int row = r0 + 32 * j;
                float4 a = pv[j * 2], c = pv[j * 2 + 1];
                uint4 st = make_uint4(bits2(__floats2bfloat162_rn(a.x, a.y)),
                                      bits2(__floats2bfloat162_rn(a.z, a.w)),
                                      bits2(__floats2bfloat162_rn(c.x, c.y)),
                                      bits2(__floats2bfloat162_rn(c.z, c.w)));
                *reinterpret_cast<uint4*>(sm + OFF_A + (size_t)row * ROWB + g8 * 16) = st;
            }
        }
        __syncthreads();

        #pragma unroll
        for (int ks = 0; ks < 4; ++ks) {
            const uint32_t ko = (uint32_t)ks * 32;
            uint32_t ah[2][4], bh[2][4];
            #pragma unroll
            for (int mi = 0; mi < 2; ++mi)
                LDSM4(ah[mi][0], ah[mi][1], ah[mi][2], ah[mi][3], aaddr[mi] + ko);
            #pragma unroll
            for (int nj = 0; nj < 2; ++nj)
                LDSM4(bh[nj][0], bh[nj][1], bh[nj][2], bh[nj][3], baddr[nj] + ko);
            #pragma unroll
            for (int nj = 0; nj < 2; ++nj)
                #pragma unroll
                for (int nk = 0; nk < 2; ++nk) {
                    const int nf = nj * 2 + nk;
                    #pragma unroll
                    for (int mi = 0; mi < 2; ++mi)
                        HMMA(acc[mi][nf], ah[mi][0], ah[mi][1], ah[mi][2], ah[mi][3],
                             bh[nj][nk], bh[nj][2 + nk]);
                }
        }
    }
    __syncthreads();   // buffer dead -> overlay usable

    // ================= fold W (own n-half) into per-row partials =================
    float* redp = reinterpret_cast<float*>(sm + OFF_REDP);
    #pragma unroll
    for (int mi = 0; mi < 2; ++mi)
        #pragma unroll
        for (int half = 0; half < 2; ++half) {
            int rl = warp_m * 32 + mi * 16 + (lane >> 2) + half * 8;   // 0..63 local
            const float* wr = wp + (size_t)(m0 + rl) * 256 + nb0 + warp_n * 32 + (lane & 3) * 2;
            float part = 0.f;
            #pragma unroll
            for (int nf = 0; nf < 4; ++nf) {
                float2 wv = __ldg(reinterpret_cast<const float2*>(
                    wr + (nf >> 1) * 16 + (nf & 1) * 8));
                part = fmaf(acc[mi][nf][half * 2 + 0], wv.x, part);
                part = fmaf(acc[mi][nf][half * 2 + 1], wv.y, part);
            }
            redp[rl * 17 + warp_n * 4 + (lane & 3)] = part;
        }
    __syncthreads();

    // reduce 16 partials per row -> this CTA's (unscaled) half-red
    float rsum = 0.f;
    if (tid < 64) {
        #pragma unroll
        for (int l = 0; l < 16; ++l) rsum += redp[tid * 17 + l];
    }

    // ================= follower: publish half-red and exit =================
    if (nh == 1) {
        if (tid < 64) {
            g_redhalf[pair * 64 + tid] = rsum;
            __threadfence();
        }
        __syncthreads();
        if (tid == 0) atomicExch(&g_pflag[pair], 1);
        return;
    }

    // ================= leader: row sums of x (direct from global) =================
    float* rssm = reinterpret_cast<float*>(sm + OFF_RS);
    float* s2sm = reinterpret_cast<float*>(sm + OFF_S2);
    #pragma unroll
    for (int j = 0; j < 8; ++j) {
        int r = wid * 8 + j;                       // 0..63 local
        const float* xr = xbp + (size_t)(m0 + r) * 256;
        float4 v0 = __ldg(reinterpret_cast<const float4*>(xr + lane * 4));
        float4 v1 = __ldg(reinterpret_cast<const float4*>(xr + 128 + lane * 4));
        float rsv = v0.x + v0.y + v0.z + v0.w + v1.x + v1.y + v1.z + v1.w;
        float s2v = v0.x * v0.x + v0.y * v0.y + v0.z * v0.z + v0.w * v0.w
                  + v1.x * v1.x + v1.y * v1.y + v1.z * v1.z + v1.w * v1.w;
        #pragma unroll
        for (int o = 16; o; o >>= 1) {
            rsv += __shfl_xor_sync(0xffffffffu, rsv, o);
            s2v += __shfl_xor_sync(0xffffffffu, s2v, o);
        }
        if (lane == 0) { rssm[r] = rsv; s2sm[r] = s2v; }
    }

    // wait for sibling's half-red
    if (tid == 0) {
        volatile int* fl = (volatile int*)&g_pflag[pair];
        while (*fl == 0) __nanosleep(32);
        __threadfence();
    }
    __syncthreads();

    // ================= merge red + BN vals =================
    float* redsm = reinterpret_cast<float*>(sm + OFF_RED);
    float vals[5] = {0.f, 0.f, 0.f, 0.f, 0.f};
    if (tid < 64) {
        float sib = g_redhalf[pair * 64 + tid];
        float red = (rsum + sib) * 0.0625f;     // 1/sqrt(256)
        redsm[tid] = red;
        float xr = rssm[tid], x2 = s2sm[tid];
        vals[0] = xr; vals[1] = x2; vals[2] = red; vals[3] = red * red; vals[4] = red * xr;
    }
    float* w8 = reinterpret_cast<float*>(sm + OFF_W8);
    #pragma unroll
    for (int qq = 0; qq < 5; ++qq) {
        float v = vals[qq];
        #pragma unroll
        for (int o = 16; o; o >>= 1) v += __shfl_xor_sync(0xffffffffu, v, o);
        if (lane == 0) w8[wid * 5 + qq] = v;
    }
    __syncthreads();
    if (tid == 32) g_pflag[pair] = 0;          // reset for next graph replay

    // ================= cross-CTA BN handshake (32 leaders per channel) =================
    float* bc = reinterpret_cast<float*>(sm + OFF_BC);
    if (tid == 0) {
        int slot = (p * 32 + b * 4 + q) * 5;
        #pragma unroll
        for (int qq = 0; qq < 5; ++qq) {
            float r = 0.f;
            for (int t = 0; t < 8; ++t) r += w8[t * 5 + qq];
            g_partials[slot + qq] = r;
        }
        __threadfence();
        int o = atomicAdd(&g_cnt[p], 1);
        if (o == 31) {
            __threadfence();
            float sx = 0.f, sx2 = 0.f, sr = 0.f, sr2 = 0.f, cr = 0.f;
            for (int c = 0; c < 32; ++c) {
                const float* qp = g_partials + (p * 32 + c) * 5;
                sx += qp[0]; sx2 += qp[1]; sr += qp[2]; sr2 += qp[3]; cr += qp[4];
            }
            const float N = (float)(B_ * S_ * D_);
            float sumy  = sx + (float)D_ * sr;
            float sumy2 = sx2 + 2.f * cr + (float)D_ * sr2;
            float mean = sumy / N;
            float var  = sumy2 / N - mean * mean;
            float sc = __ldg(gamma + p) * rsqrtf(var + 1e-5f);
            g_scale[p] = sc;
            g_bias[p]  = __ldg(beta + p) - mean * sc;
            __threadfence();
            atomicExch(&g_flag[p], 1);
        }
        volatile int* fl = (volatile int*)&g_flag[p];
        while (*fl == 0) __nanosleep(64);
        __threadfence();
        bc[0] = g_scale[p];
        bc[1] = g_bias[p];
        int o2 = atomicAdd(&g_cnt2[p], 1);
        if (o2 == 31) {        // all consumers done: reset for next graph replay
            g_flag[p] = 0; g_cnt[p] = 0; g_cnt2[p] = 0;
        }
    }
    __syncthreads();
    const float sc = bc[0], bi = bc[1];

    // ================= output: out = (x + red) * sc + bi (x direct from L2) =================
    float* ob = out + ((size_t)(b * P_ + p) << 16) + (size_t)m0 * 256;
    #pragma unroll
    for (int j = 0; j < 8; ++j) {
        int r = wid * 8 + j;
        float red = redsm[r];
        const float* xr = xbp + (size_t)(m0 + r) * 256;
        #pragma unroll
        for (int it = 0; it < 2; ++it) {
            float4 v = __ldg(reinterpret_cast<const float4*>(xr + it * 128 + lane * 4));
            v.x = fmaf(v.x + red, sc, bi);
            v.y = fmaf(v.y + red, sc, bi);
            v.z = fmaf(v.z + red, sc, bi);
            v.w = fmaf(v.w + red, sc, bi);
            *reinterpret_cast<float4*>(ob + (size_t)r * 256 + it * 128 + lane * 4) = v;
        }
    }
}

// =====================================================================
extern "C" void kernel_launch(void* const* d_in, const int* in_sizes, int n_in,
                              void* d_out, int out_size)
{
    const float* x     = (const float*)d_in[0];
    const float* w     = (const float*)d_in[1];
    const float* gamma = (const float*)d_in[2];
    const float* beta  = (const float*)d_in[3];
    float* out = (float*)d_out;

    cudaFuncSetAttribute(da_fused_kernel,
                         cudaFuncAttributeMaxDynamicSharedMemorySize, SMEM_BYTES);

    dim3 grid(64, P_);   // blockIdx.x = b*8+q*2+nh (pairs adjacent, channels contiguous)
    da_fused_kernel<<<grid, 256, SMEM_BYTES>>>(x, w, gamma, beta, out);
}